// round 5
// baseline (speedup 1.0000x reference)
#include <cuda_runtime.h>
#include <cstdint>

#define N_ROWS 8192
#define DIM    128
#define STRIDE_M 136          // padded byte stride for packed-mask smem tile
#define SM_A_BYTES   65536    // 128x128 fp32
#define SM_B_BYTES   65536    // per buffer
#define SM_M_BYTES   17408    // 128*136 per buffer
#define SMEM_TOTAL   (SM_A_BYTES + 2*SM_B_BYTES + 2*SM_M_BYTES)  // 231424

// -------- scratch (device globals: allocation-free) --------
__device__ float g_fn[N_ROWS * DIM];   // normalized features, tf32-rounded bits
__device__ float g_pos[N_ROWS];
__device__ float g_neg[N_ROWS];
__device__ float g_pcnt[N_ROWS];

// -------- helpers --------
__device__ __forceinline__ unsigned tf32_bits(float x) {
    unsigned u;
    asm("cvt.rna.tf32.f32 %0, %1;" : "=r"(u) : "f"(x));
    return u;
}
__device__ __forceinline__ float ex2f_fast(float x) {
    float r;
    asm("ex2.approx.ftz.f32 %0, %1;" : "=f"(r) : "f"(x));
    return r;
}
__device__ __forceinline__ void mma_tf32(float* d, const unsigned* a, const unsigned* b) {
    asm volatile(
        "mma.sync.aligned.m16n8k8.row.col.f32.tf32.tf32.f32 "
        "{%0,%1,%2,%3}, {%4,%5,%6,%7}, {%8,%9}, {%0,%1,%2,%3};\n"
        : "+f"(d[0]), "+f"(d[1]), "+f"(d[2]), "+f"(d[3])
        : "r"(a[0]), "r"(a[1]), "r"(a[2]), "r"(a[3]), "r"(b[0]), "r"(b[1]));
}
__device__ __forceinline__ void cp_async16(unsigned smem_addr, const void* gptr) {
    asm volatile("cp.async.cg.shared.global [%0], [%1], 16;\n" :: "r"(smem_addr), "l"(gptr));
}

// ============================================================
// Kernel 1: normalize rows, round to tf32, zero accumulators
// grid <<<128, 256>>>: 8 warps/block, 8 rows/warp
// ============================================================
__global__ void __launch_bounds__(256) normalize_kernel(const float* __restrict__ f) {
    int gtid = blockIdx.x * 256 + threadIdx.x;
    if (gtid < N_ROWS) { g_pos[gtid] = 0.f; g_neg[gtid] = 0.f; g_pcnt[gtid] = 0.f; }

    int wid = threadIdx.x >> 5, lane = threadIdx.x & 31;
    int rbase = blockIdx.x * 64 + wid * 8;
    for (int i = 0; i < 8; i++) {
        int r = rbase + i;
        float4 v = *(const float4*)(f + r * DIM + lane * 4);
        float ss = v.x * v.x + v.y * v.y + v.z * v.z + v.w * v.w;
        #pragma unroll
        for (int o = 16; o; o >>= 1) ss += __shfl_xor_sync(0xFFFFFFFFu, ss, o);
        float s = 1.0f / fmaxf(sqrtf(ss), 1e-8f);
        uint4 o4;
        o4.x = tf32_bits(v.x * s);
        o4.y = tf32_bits(v.y * s);
        o4.z = tf32_bits(v.z * s);
        o4.w = tf32_bits(v.w * s);
        *(uint4*)(g_fn + r * DIM + lane * 4) = o4;
    }
}

// ============================================================
// Kernel 2: fused GEMM + exp + masked row-sums
// grid dim3(2, 64): blockIdx.x = column group (4096 cols),
//                   blockIdx.y = 128-row strip.
// 384 threads: warps 0-7 consumers (2x4 warp grid, 64x32 warp tiles),
//              warps 8-11 producers (mask stream + B prefetch).
// ============================================================
__global__ void __launch_bounds__(384, 1)
ssntxent_main(const int* __restrict__ pmask, const int* __restrict__ nmask) {
    extern __shared__ char smem[];
    float* sA = (float*)smem;                                   // [128][128] swizzled
    float* sB = (float*)(smem + SM_A_BYTES);                    // 2 x [128][128] swizzled
    unsigned char* sM = (unsigned char*)(smem + SM_A_BYTES + 2 * SM_B_BYTES); // 2 x [128][136]

    const int tid  = threadIdx.x;
    const int wid  = tid >> 5;
    const int lane = tid & 31;
    const int i0   = blockIdx.y * 128;        // global row base of strip
    const int cgb  = blockIdx.x * 4096;       // global col base of group
    const float K2 = 20.6100944444973f;       // 1 / (0.07 * ln 2)

    // ---------------- producer routines ----------------
    // B tile for j-tile jt into buffer buf (fn rows cgb+jt*128 .. +127)
    auto produceB = [&](int jt, int buf) {
        const float* src = g_fn + (cgb + jt * 128) * DIM;
        unsigned dbase = (unsigned)__cvta_generic_to_shared(sB + buf * 16384);
        int tIdx = (wid - 8) * 32 + lane;     // 0..127
        #pragma unroll
        for (int k = 0; k < 32; k++) {
            int chunk = tIdx + k * 128;       // 0..4095, 16B each
            int r = chunk >> 5;
            int c4 = (chunk & 31) << 2;
            unsigned daddr = dbase + (unsigned)((r * 128 + (c4 ^ ((r & 7) << 2))) * 4);
            cp_async16(daddr, src + r * DIM + c4);
        }
        asm volatile("cp.async.commit_group;\n");
    };
    // packed masks for j-tile jt into buffer buf. 1 byte per (i,j): pm | nm<<1,
    // diagonal zeroed. Coalesced LDG.128 (one row of one mask per warp-instr).
    auto produceM = [&](int jt, int buf) {
        const int c0 = cgb + jt * 128;
        unsigned char* mdst = sM + buf * SM_M_BYTES;
        const int pwid = wid - 8;
        const int col = c0 + 4 * lane;
        #pragma unroll 1
        for (int rr0 = 0; rr0 < 32; rr0 += 8) {
            int4 a[8], b[8];
            #pragma unroll
            for (int u = 0; u < 8; u++) {
                int rl = pwid * 32 + rr0 + u;
                int off = (i0 + rl) * N_ROWS + col;
                a[u] = *(const int4*)(pmask + off);
                b[u] = *(const int4*)(nmask + off);
            }
            #pragma unroll
            for (int u = 0; u < 8; u++) {
                int rl = pwid * 32 + rr0 + u;
                unsigned v = (unsigned)((a[u].x & 1)        | ((b[u].x & 1) << 1)
                                      | ((a[u].y & 1) << 8)  | ((b[u].y & 1) << 9)
                                      | ((a[u].z & 1) << 16) | ((b[u].z & 1) << 17)
                                      | ((a[u].w & 1) << 24) | ((b[u].w & 1) << 25));
                int d = (i0 + rl) - col;      // diagonal: zero both bits
                if ((unsigned)d < 4u) v &= ~(3u << (d * 8));
                *(unsigned*)(mdst + rl * STRIDE_M + 4 * lane) = v;
            }
        }
    };

    // ---------------- prologue ----------------
    if (wid < 8) {
        // consumers fill the persistent A strip (fn rows i0..i0+127), swizzled
        for (int idx = tid; idx < 4096; idx += 256) {
            int r = idx >> 5;
            int c4 = (idx & 31) << 2;
            float4 v = *(const float4*)(g_fn + (i0 + r) * DIM + c4);
            *(float4*)(sA + r * 128 + (c4 ^ ((r & 7) << 2))) = v;
        }
    } else {
        produceB(0, 0);
        produceM(0, 0);
        asm volatile("cp.async.wait_group 0;\n" ::: "memory");
    }
    __syncthreads();

    // ---------------- main pipeline over 32 j-tiles ----------------
    const int wm = wid >> 2;        // 0..1 (consumer)
    const int wn = wid & 3;         // 0..3
    const int g = lane >> 2;        // 0..7
    const int t = lane & 3;         // 0..3
    const int sw = g << 2;          // per-thread swizzle XOR (row&7 == g always)

    for (int j = 0; j < 32; j++) {
        const int buf = j & 1;
        if (wid >= 8) {
            if (j + 1 < 32) {
                produceB(j + 1, buf ^ 1);
                produceM(j + 1, buf ^ 1);
                asm volatile("cp.async.wait_group 0;\n" ::: "memory");
            }
        } else {
            // -------- MMA: warp tile 64x32, K = 128 --------
            float acc[4][4][4];
            #pragma unroll
            for (int mf = 0; mf < 4; mf++)
                #pragma unroll
                for (int nf = 0; nf < 4; nf++)
                    #pragma unroll
                    for (int e = 0; e < 4; e++) acc[mf][nf][e] = 0.f;

            const float* Bsb = sB + buf * 16384;
            #pragma unroll 2
            for (int kk = 0; kk < 16; kk++) {
                const int c0s = (8 * kk + t) ^ sw;
                const int c1s = (8 * kk + t + 4) ^ sw;
                unsigned a[4][4];
                #pragma unroll
                for (int mf = 0; mf < 4; mf++) {
                    int rA = wm * 64 + mf * 16 + g;
                    a[mf][0] = __float_as_uint(sA[rA * 128 + c0s]);
                    a[mf][1] = __float_as_uint(sA[(rA + 8) * 128 + c0s]);
                    a[mf][2] = __float_as_uint(sA[rA * 128 + c1s]);
                    a[mf][3] = __float_as_uint(sA[(rA + 8) * 128 + c1s]);
                }
                unsigned b[4][2];
                #pragma unroll
                for (int nf = 0; nf < 4; nf++) {
                    int rB = wn * 32 + nf * 8 + g;
                    b[nf][0] = __float_as_uint(Bsb[rB * 128 + c0s]);
                    b[nf][1] = __float_as_uint(Bsb[rB * 128 + c1s]);
                }
                #pragma unroll
                for (int mf = 0; mf < 4; mf++)
                    #pragma unroll
                    for (int nf = 0; nf < 4; nf++)
                        mma_tf32(acc[mf][nf], a[mf], b[nf]);
            }

            // -------- epilogue: exp + masked row sums --------
            const unsigned char* Ms = sM + buf * SM_M_BYTES;
            #pragma unroll
            for (int mf = 0; mf < 4; mf++) {
                #pragma unroll
                for (int h = 0; h < 2; h++) {
                    int rl = wm * 64 + mf * 16 + 8 * h + g;
                    float pp = 0.f, nn = 0.f, pc = 0.f;
                    #pragma unroll
                    for (int nf = 0; nf < 4; nf++) {
                        int cl = wn * 32 + nf * 8 + 2 * t;
                        unsigned m = *(const unsigned short*)(Ms + rl * STRIDE_M + cl);
                        float e0 = ex2f_fast(acc[mf][nf][2 * h + 0] * K2);
                        float e1 = ex2f_fast(acc[mf][nf][2 * h + 1] * K2);
                        float p0 = (float)(m & 1u),        q0 = (float)((m >> 1) & 1u);
                        float p1 = (float)((m >> 8) & 1u), q1 = (float)((m >> 9) & 1u);
                        pp = fmaf(e0, p0, pp); pp = fmaf(e1, p1, pp);
                        nn = fmaf(e0, q0, nn); nn = fmaf(e1, q1, nn);
                        pc += p0 + p1;
                    }
                    // quad reduce (4 lanes cover the warp's 32 cols of this row)
                    pp += __shfl_xor_sync(0xFFFFFFFFu, pp, 1);
                    pp += __shfl_xor_sync(0xFFFFFFFFu, pp, 2);
                    nn += __shfl_xor_sync(0xFFFFFFFFu, nn, 1);
                    nn += __shfl_xor_sync(0xFFFFFFFFu, nn, 2);
                    pc += __shfl_xor_sync(0xFFFFFFFFu, pc, 1);
                    pc += __shfl_xor_sync(0xFFFFFFFFu, pc, 2);
                    if (t == 0) {
                        atomicAdd(&g_pos[i0 + rl], pp);
                        atomicAdd(&g_neg[i0 + rl], nn);
                        atomicAdd(&g_pcnt[i0 + rl], pc);
                    }
                }
            }
        }
        __syncthreads();
    }
}

// ============================================================
// Kernel 3: loss = -mean( log(pos/(pos+neg)) / pcnt )
// ============================================================
__global__ void __launch_bounds__(256) finalize_kernel(float* __restrict__ out) {
    int tid = threadIdx.x;
    double s = 0.0;
    for (int r = tid; r < N_ROWS; r += 256) {
        float P = g_pos[r], Nn = g_neg[r], C = g_pcnt[r];
        s += (double)(logf(P / (P + Nn)) / C);
    }
    __shared__ double red[256];
    red[tid] = s;
    __syncthreads();
    for (int o = 128; o; o >>= 1) {
        if (tid < o) red[tid] += red[tid + o];
        __syncthreads();
    }
    if (tid == 0) out[0] = (float)(-red[0] / (double)N_ROWS);
}

// ============================================================
extern "C" void kernel_launch(void* const* d_in, const int* in_sizes, int n_in,
                              void* d_out, int out_size) {
    const float* features = (const float*)d_in[0];
    const int* pmask = (const int*)d_in[1];
    const int* nmask = (const int*)d_in[2];
    float* out = (float*)d_out;

    cudaFuncSetAttribute(ssntxent_main,
                         cudaFuncAttributeMaxDynamicSharedMemorySize, SMEM_TOTAL);

    normalize_kernel<<<128, 256>>>(features);
    ssntxent_main<<<dim3(2, 64), 384, SMEM_TOTAL>>>(pmask, nmask);
    finalize_kernel<<<1, 256>>>(out);
}

// round 7
// speedup vs baseline: 1.1802x; 1.1802x over previous
#include <cuda_runtime.h>
#include <cuda_bf16.h>
#include <cstdint>

#define N_ROWS 8192
#define DIM    128

// ---- dynamic smem layout ----
#define OFF_A      0                        // 128x128 bf16 A strip (32KB), swizzled
#define OFF_B      32768                    // 2 x 32KB B tiles
#define STRIDE_M   132                      // mask row stride (33 words)
#define SM_M_BYTES (128 * STRIDE_M)         // 16896
#define OFF_M      (32768 + 2 * 32768)      // 98304
#define SMEM_TOTAL (OFF_M + 2 * SM_M_BYTES) // 132096

// -------- scratch (device globals: allocation-free) --------
__device__ __nv_bfloat16 g_fnb[N_ROWS * DIM];   // normalized features (bf16)
__device__ float g_pos[N_ROWS];
__device__ float g_neg[N_ROWS];
__device__ float g_pcnt[N_ROWS];

// ---------------- helpers ----------------
__device__ __forceinline__ float ex2f_fast(float x) {
    float r; asm("ex2.approx.ftz.f32 %0, %1;" : "=f"(r) : "f"(x)); return r;
}
__device__ __forceinline__ void cp_async16(unsigned smem_addr, const void* gptr) {
    asm volatile("cp.async.cg.shared.global [%0], [%1], 16;\n" :: "r"(smem_addr), "l"(gptr));
}
__device__ __forceinline__ uint32_t smem_u32(const void* p) {
    uint32_t a;
    asm("{ .reg .u64 t; cvta.to.shared.u64 t, %1; cvt.u32.u64 %0, t; }" : "=r"(a) : "l"(p));
    return a;
}
__device__ __forceinline__ void ldsm_x4(unsigned* r, uint32_t addr) {
    asm volatile("ldmatrix.sync.aligned.m8n8.x4.shared.b16 {%0,%1,%2,%3}, [%4];"
                 : "=r"(r[0]), "=r"(r[1]), "=r"(r[2]), "=r"(r[3]) : "r"(addr));
}
__device__ __forceinline__ void mma_bf16(float* d, const unsigned* a, const unsigned* b) {
    asm volatile(
        "mma.sync.aligned.m16n8k16.row.col.f32.bf16.bf16.f32 "
        "{%0,%1,%2,%3}, {%4,%5,%6,%7}, {%8,%9}, {%0,%1,%2,%3};\n"
        : "+f"(d[0]), "+f"(d[1]), "+f"(d[2]), "+f"(d[3])
        : "r"(a[0]), "r"(a[1]), "r"(a[2]), "r"(a[3]), "r"(b[0]), "r"(b[1]));
}
// swizzled byte offset within a 128x128 bf16 tile: row r (0..127), 16B chunk c (0..15)
__device__ __forceinline__ unsigned tile_off(int r, int c) {
    return (unsigned)(r * 256 + ((c ^ (r & 7)) << 4));
}

// ============================================================
// Kernel 1: normalize rows -> bf16, zero accumulators
// grid 1024 x 256 (8 warps/block, 1 row/warp)
// ============================================================
__global__ void __launch_bounds__(256) normalize_kernel(const float* __restrict__ f) {
    int g = blockIdx.x * 256 + threadIdx.x;
    if (g < N_ROWS) { g_pos[g] = 0.f; g_neg[g] = 0.f; g_pcnt[g] = 0.f; }
    int row = blockIdx.x * 8 + (threadIdx.x >> 5);
    int lane = threadIdx.x & 31;
    float4 v = *(const float4*)(f + row * DIM + lane * 4);
    float ss = fmaf(v.x, v.x, fmaf(v.y, v.y, fmaf(v.z, v.z, v.w * v.w)));
    #pragma unroll
    for (int o = 16; o; o >>= 1) ss += __shfl_xor_sync(0xFFFFFFFFu, ss, o);
    float s = 1.0f / fmaxf(sqrtf(ss), 1e-8f);
    unsigned lo, hi;  // pack: first src -> high half
    asm("cvt.rn.bf16x2.f32 %0, %1, %2;" : "=r"(lo) : "f"(v.y * s), "f"(v.x * s));
    asm("cvt.rn.bf16x2.f32 %0, %1, %2;" : "=r"(hi) : "f"(v.w * s), "f"(v.z * s));
    uint2 o2; o2.x = lo; o2.y = hi;
    *(uint2*)(g_fnb + row * DIM + lane * 4) = o2;
}

// ============================================================
// Kernel 2: fused bf16-MMA GEMM + exp + masked row-sums
// grid dim3(2, 64): blockIdx.x = 4096-col group, blockIdx.y = 128-row strip.
// 384 threads: warps 0-7 consumers (2x4 grid, 64x32 warp tiles),
//              warps 8-11 producers (mask pack + B prefetch).
// ============================================================
__global__ void __launch_bounds__(384, 1)
ssntxent_main(const int* __restrict__ pmask, const int* __restrict__ nmask) {
    extern __shared__ char smem[];
    const int tid  = threadIdx.x;
    const int wid  = tid >> 5;
    const int lane = tid & 31;
    const int i0   = blockIdx.y * 128;
    const int cgb  = blockIdx.x * 4096;
    const float K2 = 20.6100944444973f;   // 1 / (0.07 * ln 2)
    const uint32_t smem_base = smem_u32(smem);

    // ---------------- producers ----------------
    auto produceB = [&](int jt, int b) {
        const __nv_bfloat16* src = g_fnb + (cgb + jt * 128) * DIM;
        unsigned dbase = smem_base + OFF_B + (unsigned)b * 32768u;
        int tIdx = (wid - 8) * 32 + lane;                  // 0..127
        #pragma unroll
        for (int k = 0; k < 16; k++) {
            int idx = tIdx + k * 128;                      // 0..2047
            int r = idx >> 4, c = idx & 15;
            cp_async16(dbase + tile_off(r, c), src + r * DIM + c * 8);
        }
        asm volatile("cp.async.commit_group;\n");
    };
    auto produceM = [&](int jt, int b) {
        const int c0 = cgb + jt * 128;
        unsigned char* mdst = (unsigned char*)smem + OFF_M + b * SM_M_BYTES;
        const int pwid = wid - 8;
        const int col = c0 + 4 * lane;
        #pragma unroll 1
        for (int rr0 = 0; rr0 < 32; rr0 += 8) {
            int4 a[8], bb[8];
            #pragma unroll
            for (int u = 0; u < 8; u++) {
                int rl = pwid * 32 + rr0 + u;
                int off = (i0 + rl) * N_ROWS + col;
                a[u]  = *(const int4*)(pmask + off);
                bb[u] = *(const int4*)(nmask + off);
            }
            #pragma unroll
            for (int u = 0; u < 8; u++) {
                int rl = pwid * 32 + rr0 + u;
                unsigned v = (unsigned)((a[u].x & 1)         | ((bb[u].x & 1) << 1)
                                      | ((a[u].y & 1) << 8)  | ((bb[u].y & 1) << 9)
                                      | ((a[u].z & 1) << 16) | ((bb[u].z & 1) << 17)
                                      | ((a[u].w & 1) << 24) | ((bb[u].w & 1) << 25));
                int d = (i0 + rl) - col;
                if ((unsigned)d < 4u) v &= ~(3u << (d * 8));
                *(unsigned*)(mdst + rl * STRIDE_M + 4 * lane) = v;
            }
        }
    };

    // ---------------- prologue ----------------
    if (wid < 8) {
        // consumers fill persistent A strip (rows i0..i0+127), swizzled bf16
        for (int idx = tid; idx < 2048; idx += 256) {
            int r = idx >> 4, c = idx & 15;
            uint4 v = *(const uint4*)(g_fnb + (i0 + r) * DIM + c * 8);
            *(uint4*)(smem + OFF_A + tile_off(r, c)) = v;
        }
    } else {
        produceB(0, 0);
        asm volatile("cp.async.wait_group 0;\n" ::: "memory");
        produceM(0, 0);
    }
    __syncthreads();

    // consumer lane geometry
    const int wm = wid >> 2, wn = wid & 3;
    const int g = lane >> 2, t = lane & 3;
    // ldmatrix per-lane address parts
    const int arow = wm * 64 + ((lane >> 3) & 1) * 8 + (lane & 7);   // + mf*16
    const uint32_t aBase = smem_base + OFF_A + (unsigned)(arow * 256);
    const int achunk = (lane >> 4);                                  // +2*kk, ^ (lane&7)
    const int brow0 = wn * 32 + ((lane >> 4) << 3) + (lane & 7);     // + p*16
    const int bchunk = (lane >> 3) & 1;                              // +2*kk, ^ (lane&7)
    const int sx = lane & 7;

    // persistent per-thread row accumulators: rows (mf,h) -> wm*64+mf*16+8h+g
    float accP[8], accN[8], accC[8];
    #pragma unroll
    for (int i = 0; i < 8; i++) { accP[i] = 0.f; accN[i] = 0.f; accC[i] = 0.f; }

    // ---------------- main pipeline over 32 j-tiles ----------------
    for (int j = 0; j < 32; j++) {
        const int buf = j & 1;
        if (wid >= 8) {
            if (j + 1 < 32) {
                produceB(j + 1, buf ^ 1);
                produceM(j + 1, buf ^ 1);
                asm volatile("cp.async.wait_group 0;\n" ::: "memory");
            }
        } else {
            // -------- MMA: warp tile 64x32, K = 128 (bf16 m16n8k16) --------
            float acc[4][4][4];
            #pragma unroll
            for (int mf = 0; mf < 4; mf++)
                #pragma unroll
                for (int nf = 0; nf < 4; nf++)
                    #pragma unroll
                    for (int e = 0; e < 4; e++) acc[mf][nf][e] = 0.f;

            const uint32_t bBase = smem_base + OFF_B + (unsigned)buf * 32768u
                                 + (unsigned)(brow0 * 256);
            #pragma unroll
            for (int kk = 0; kk < 8; kk++) {
                unsigned a[4][4], b[2][4];
                #pragma unroll
                for (int mf = 0; mf < 4; mf++)
                    ldsm_x4(a[mf], aBase + (unsigned)(mf * 16 * 256)
                                 + (unsigned)(((2 * kk + achunk) ^ sx) << 4));
                #pragma unroll
                for (int p = 0; p < 2; p++)
                    ldsm_x4(b[p], bBase + (unsigned)(p * 16 * 256)
                                + (unsigned)(((2 * kk + bchunk) ^ sx) << 4));
                #pragma unroll
                for (int mf = 0; mf < 4; mf++) {
                    mma_bf16(acc[mf][0], a[mf], &b[0][0]);
                    mma_bf16(acc[mf][1], a[mf], &b[0][2]);
                    mma_bf16(acc[mf][2], a[mf], &b[1][0]);
                    mma_bf16(acc[mf][3], a[mf], &b[1][2]);
                }
            }

            // -------- epilogue: exp + masked sums into register row accs --------
            const unsigned char* Ms =
                (const unsigned char*)smem + OFF_M + buf * SM_M_BYTES;
            #pragma unroll
            for (int mf = 0; mf < 4; mf++) {
                #pragma unroll
                for (int h = 0; h < 2; h++) {
                    const int ri = mf * 2 + h;
                    const int rl = wm * 64 + mf * 16 + 8 * h + g;
                    const unsigned char* Mrow = Ms + rl * STRIDE_M + wn * 32 + 2 * t;
                    #pragma unroll
                    for (int nf = 0; nf < 4; nf++) {
                        unsigned m = *(const unsigned short*)(Mrow + nf * 8);
                        float e0 = ex2f_fast(acc[mf][nf][2 * h + 0] * K2);
                        float e1 = ex2f_fast(acc[mf][nf][2 * h + 1] * K2);
                        float p0 = (float)(m & 1u),        q0 = (float)((m >> 1) & 1u);
                        float p1 = (float)((m >> 8) & 1u), q1 = (float)((m >> 9) & 1u);
                        accP[ri] = fmaf(e0, p0, accP[ri]);
                        accP[ri] = fmaf(e1, p1, accP[ri]);
                        accN[ri] = fmaf(e0, q0, accN[ri]);
                        accN[ri] = fmaf(e1, q1, accN[ri]);
                        accC[ri] += p0 + p1;
                    }
                }
            }
        }
        __syncthreads();
    }

    // ---------------- writeback: reduce over t, one atomic set ----------------
    if (wid < 8) {
        #pragma unroll
        for (int ri = 0; ri < 8; ri++) {
            float pp = accP[ri], nn = accN[ri], pc = accC[ri];
            pp += __shfl_xor_sync(0xFFFFFFFFu, pp, 1);
            pp += __shfl_xor_sync(0xFFFFFFFFu, pp, 2);
            nn += __shfl_xor_sync(0xFFFFFFFFu, nn, 1);
            nn += __shfl_xor_sync(0xFFFFFFFFu, nn, 2);
            pc += __shfl_xor_sync(0xFFFFFFFFu, pc, 1);
            pc += __shfl_xor_sync(0xFFFFFFFFu, pc, 2);
            if (t == 0) {
                int row = i0 + wm * 64 + (ri >> 1) * 16 + (ri & 1) * 8 + g;
                atomicAdd(&g_pos[row], pp);
                atomicAdd(&g_neg[row], nn);
                atomicAdd(&g_pcnt[row], pc);
            }
        }
    }
}

// ============================================================
// Kernel 3: loss = -mean( log(pos/(pos+neg)) / pcnt )
// ============================================================
__global__ void __launch_bounds__(256) finalize_kernel(float* __restrict__ out) {
    int tid = threadIdx.x;
    double s = 0.0;
    for (int r = tid; r < N_ROWS; r += 256) {
        float P = g_pos[r], Nn = g_neg[r], C = g_pcnt[r];
        s += (double)(logf(P / (P + Nn)) / C);
    }
    __shared__ double red[256];
    red[tid] = s;
    __syncthreads();
    for (int o = 128; o; o >>= 1) {
        if (tid < o) red[tid] += red[tid + o];
        __syncthreads();
    }
    if (tid == 0) out[0] = (float)(-red[0] / (double)N_ROWS);
}

// ============================================================
extern "C" void kernel_launch(void* const* d_in, const int* in_sizes, int n_in,
                              void* d_out, int out_size) {
    const float* features = (const float*)d_in[0];
    const int* pmask = (const int*)d_in[1];
    const int* nmask = (const int*)d_in[2];
    float* out = (float*)d_out;

    cudaFuncSetAttribute(ssntxent_main,
                         cudaFuncAttributeMaxDynamicSharedMemorySize, SMEM_TOTAL);

    normalize_kernel<<<1024, 256>>>(features);
    ssntxent_main<<<dim3(2, 64), 384, SMEM_TOTAL>>>(pmask, nmask);
    finalize_kernel<<<1, 256>>>(out);
}

// round 10
// speedup vs baseline: 1.4396x; 1.2198x over previous
#include <cuda_runtime.h>
#include <cuda_bf16.h>
#include <cstdint>

#define N_ROWS 8192
#define DIM    128

// ---- dynamic smem layout ----
#define OFF_A      0                        // 128x128 bf16 A strip (32KB), swizzled
#define OFF_B      32768                    // 2 x 32KB B tiles
#define STRIDE_M   132                      // mask row stride (33 words)
#define SM_M_BYTES (128 * STRIDE_M)         // 16896
#define OFF_M      (32768 + 2 * 32768)      // 98304
#define SMEM_TOTAL (OFF_M + 2 * SM_M_BYTES) // 132096

// -------- scratch (device globals: allocation-free) --------
__device__ __nv_bfloat16 g_fnb[N_ROWS * DIM];   // normalized features (bf16)
__device__ float g_pos[N_ROWS];
__device__ float g_neg[N_ROWS];
__device__ float g_pcnt[N_ROWS];

// ---------------- helpers ----------------
__device__ __forceinline__ float ex2f_fast(float x) {
    float r; asm("ex2.approx.ftz.f32 %0, %1;" : "=f"(r) : "f"(x)); return r;
}
__device__ __forceinline__ void cp_async16(unsigned smem_addr, const void* gptr) {
    asm volatile("cp.async.cg.shared.global [%0], [%1], 16;\n" :: "r"(smem_addr), "l"(gptr));
}
__device__ __forceinline__ uint32_t smem_u32(const void* p) {
    uint32_t a;
    asm("{ .reg .u64 t; cvta.to.shared.u64 t, %1; cvt.u32.u64 %0, t; }" : "=r"(a) : "l"(p));
    return a;
}
__device__ __forceinline__ void ldsm_x4(unsigned* r, uint32_t addr) {
    asm volatile("ldmatrix.sync.aligned.m8n8.x4.shared.b16 {%0,%1,%2,%3}, [%4];"
                 : "=r"(r[0]), "=r"(r[1]), "=r"(r[2]), "=r"(r[3]) : "r"(addr));
}
__device__ __forceinline__ void mma_bf16(float* d, const unsigned* a, const unsigned* b) {
    asm volatile(
        "mma.sync.aligned.m16n8k16.row.col.f32.bf16.bf16.f32 "
        "{%0,%1,%2,%3}, {%4,%5,%6,%7}, {%8,%9}, {%0,%1,%2,%3};\n"
        : "+f"(d[0]), "+f"(d[1]), "+f"(d[2]), "+f"(d[3])
        : "r"(a[0]), "r"(a[1]), "r"(a[2]), "r"(a[3]), "r"(b[0]), "r"(b[1]));
}
// swizzled byte offset within a 128x128 bf16 tile: row r (0..127), 16B chunk c (0..15)
__device__ __forceinline__ unsigned tile_off(int r, int c) {
    return (unsigned)(r * 256 + ((c ^ (r & 7)) << 4));
}

// ============================================================
// Kernel 1: normalize rows -> bf16, zero accumulators
// ============================================================
__global__ void __launch_bounds__(256) normalize_kernel(const float* __restrict__ f) {
    int g = blockIdx.x * 256 + threadIdx.x;
    if (g < N_ROWS) { g_pos[g] = 0.f; g_neg[g] = 0.f; g_pcnt[g] = 0.f; }
    int row = blockIdx.x * 8 + (threadIdx.x >> 5);
    int lane = threadIdx.x & 31;
    float4 v = *(const float4*)(f + row * DIM + lane * 4);
    float ss = fmaf(v.x, v.x, fmaf(v.y, v.y, fmaf(v.z, v.z, v.w * v.w)));
    #pragma unroll
    for (int o = 16; o; o >>= 1) ss += __shfl_xor_sync(0xFFFFFFFFu, ss, o);
    float s = 1.0f / fmaxf(sqrtf(ss), 1e-8f);
    unsigned lo, hi;  // cvt packs: first source -> high half
    asm("cvt.rn.bf16x2.f32 %0, %1, %2;" : "=r"(lo) : "f"(v.y * s), "f"(v.x * s));
    asm("cvt.rn.bf16x2.f32 %0, %1, %2;" : "=r"(hi) : "f"(v.w * s), "f"(v.z * s));
    uint2 o2; o2.x = lo; o2.y = hi;
    *(uint2*)(g_fnb + row * DIM + lane * 4) = o2;
}

// ============================================================
// Kernel 2: fused bf16-MMA GEMM + exp + masked row-sums.
// grid dim3(2, 64); 512 threads: warps 0-7 consumers (2x4 grid, 64x32 tiles,
// processed as two 32-row halves), warps 8-15 producers (16 mask rows each).
// Each launch handles 16 j-tiles [j0, j0+16); accumulators persist in gmem.
// ============================================================
__global__ void __launch_bounds__(512, 1)
ssntxent_main(const int* __restrict__ pmask, const int* __restrict__ nmask, int j0) {
    extern __shared__ char smem[];
    const int tid  = threadIdx.x;
    const int wid  = tid >> 5;
    const int lane = tid & 31;
    const int i0   = blockIdx.y * 128;
    const int cgb  = blockIdx.x * 4096;
    const float K2 = 20.6100944444973f;   // 1 / (0.07 * ln 2)
    const uint32_t smem_base = smem_u32(smem);

    // ---------------- producers (warps 8-15) ----------------
    auto produceB = [&](int jt, int b) {
        const __nv_bfloat16* src = g_fnb + (cgb + jt * 128) * DIM;
        unsigned dbase = smem_base + OFF_B + (unsigned)b * 32768u;
        int tIdx = (wid - 8) * 32 + lane;                  // 0..255
        #pragma unroll
        for (int k = 0; k < 8; k++) {
            int idx = tIdx + k * 256;                      // 0..2047
            int r = idx >> 4, c = idx & 15;
            cp_async16(dbase + tile_off(r, c), src + r * DIM + c * 8);
        }
        asm volatile("cp.async.commit_group;\n");
    };
    // pack masks for j-tile jt into buffer b: 1 byte/(i,j): pm | nm<<1, diag zeroed.
    // 8 producer warps x 16 rows; 2 batches of 8 rows (16 LDG.128 in flight each).
    auto produceM = [&](int jt, int b) {
        const int c0 = cgb + jt * 128;
        unsigned char* mdst = (unsigned char*)smem + OFF_M + b * SM_M_BYTES;
        const int pwid = wid - 8;                          // 0..7
        const int col = c0 + 4 * lane;
        #pragma unroll 1
        for (int b2 = 0; b2 < 2; b2++) {
            int4 a[8], bb[8];
            #pragma unroll
            for (int u = 0; u < 8; u++) {
                int rl = pwid * 16 + b2 * 8 + u;
                int off = (i0 + rl) * N_ROWS + col;
                a[u]  = *(const int4*)(pmask + off);
                bb[u] = *(const int4*)(nmask + off);
            }
            #pragma unroll
            for (int u = 0; u < 8; u++) {
                int rl = pwid * 16 + b2 * 8 + u;
                unsigned v = (unsigned)((a[u].x & 1)         | ((bb[u].x & 1) << 1)
                                      | ((a[u].y & 1) << 8)  | ((bb[u].y & 1) << 9)
                                      | ((a[u].z & 1) << 16) | ((bb[u].z & 1) << 17)
                                      | ((a[u].w & 1) << 24) | ((bb[u].w & 1) << 25));
                int d = (i0 + rl) - col;
                if ((unsigned)d < 4u) v &= ~(3u << (d * 8));
                *(unsigned*)(mdst + rl * STRIDE_M + 4 * lane) = v;
            }
        }
    };

    // ---------------- prologue ----------------
    if (wid < 8) {
        // consumers fill persistent A strip (rows i0..i0+127), swizzled bf16
        for (int idx = tid; idx < 2048; idx += 256) {
            int r = idx >> 4, c = idx & 15;
            uint4 v = *(const uint4*)(g_fnb + (i0 + r) * DIM + c * 8);
            *(uint4*)(smem + OFF_A + tile_off(r, c)) = v;
        }
    } else {
        produceB(j0, 0);
        asm volatile("cp.async.wait_group 0;\n" ::: "memory");
        produceM(j0, 0);
    }
    __syncthreads();

    // consumer lane geometry (validated layout from R6)
    const int wm = wid >> 2, wn = wid & 3;
    const int g = lane >> 2, t = lane & 3;
    const int arow = wm * 64 + ((lane >> 3) & 1) * 8 + (lane & 7);   // + (2*mh+mf)*16
    const uint32_t aBase = smem_base + OFF_A + (unsigned)(arow * 256);
    const int achunk = (lane >> 4);                                  // +2*kk, ^ sx
    const int brow0 = wn * 32 + ((lane >> 4) << 3) + (lane & 7);     // + p*16
    const int bchunk = (lane >> 3) & 1;                              // +2*kk, ^ sx
    const int sx = lane & 7;

    // persistent per-thread row accumulators: ri -> row wm*64 + (ri>>1)*16 + (ri&1)*8 + g
    float accP[8], accN[8], accC[8];
    #pragma unroll
    for (int i = 0; i < 8; i++) { accP[i] = 0.f; accN[i] = 0.f; accC[i] = 0.f; }

    // ---------------- main pipeline over 16 j-tiles ----------------
    for (int jj = 0; jj < 16; jj++) {
        const int buf = jj & 1;
        if (wid >= 8) {
            if (jj + 1 < 16) {
                produceB(j0 + jj + 1, buf ^ 1);
                produceM(j0 + jj + 1, buf ^ 1);
                asm volatile("cp.async.wait_group 0;\n" ::: "memory");
            }
        } else {
            const uint32_t bBase = smem_base + OFF_B + (unsigned)buf * 32768u
                                 + (unsigned)(brow0 * 256);
            const unsigned char* Ms =
                (const unsigned char*)smem + OFF_M + buf * SM_M_BYTES;

            #pragma unroll
            for (int mh = 0; mh < 2; mh++) {              // two 32-row halves
                float acc[2][4][4];
                #pragma unroll
                for (int mf = 0; mf < 2; mf++)
                    #pragma unroll
                    for (int nf = 0; nf < 4; nf++)
                        #pragma unroll
                        for (int e = 0; e < 4; e++) acc[mf][nf][e] = 0.f;

                #pragma unroll
                for (int kk = 0; kk < 8; kk++) {
                    unsigned a[2][4], b[2][4];
                    #pragma unroll
                    for (int mf = 0; mf < 2; mf++)
                        ldsm_x4(a[mf], aBase + (unsigned)((2 * mh + mf) * 16 * 256)
                                     + (unsigned)(((2 * kk + achunk) ^ sx) << 4));
                    #pragma unroll
                    for (int p = 0; p < 2; p++)
                        ldsm_x4(b[p], bBase + (unsigned)(p * 16 * 256)
                                    + (unsigned)(((2 * kk + bchunk) ^ sx) << 4));
                    #pragma unroll
                    for (int mf = 0; mf < 2; mf++) {
                        mma_bf16(acc[mf][0], a[mf], &b[0][0]);
                        mma_bf16(acc[mf][1], a[mf], &b[0][2]);
                        mma_bf16(acc[mf][2], a[mf], &b[1][0]);
                        mma_bf16(acc[mf][3], a[mf], &b[1][2]);
                    }
                }

                // epilogue for this half: exp + masked sums into register accs
                #pragma unroll
                for (int mf = 0; mf < 2; mf++) {
                    #pragma unroll
                    for (int h = 0; h < 2; h++) {
                        const int ri = (2 * mh + mf) * 2 + h;
                        const int rl = wm * 64 + (2 * mh + mf) * 16 + 8 * h + g;
                        const unsigned char* Mrow = Ms + rl * STRIDE_M + wn * 32 + 2 * t;
                        #pragma unroll
                        for (int nf = 0; nf < 4; nf++) {
                            unsigned m = *(const unsigned short*)(Mrow + nf * 8);
                            float e0 = ex2f_fast(acc[mf][nf][2 * h + 0] * K2);
                            float e1 = ex2f_fast(acc[mf][nf][2 * h + 1] * K2);
                            float p0 = (float)(m & 1u),        q0 = (float)((m >> 1) & 1u);
                            float p1 = (float)((m >> 8) & 1u), q1 = (float)((m >> 9) & 1u);
                            accP[ri] = fmaf(e0, p0, accP[ri]);
                            accP[ri] = fmaf(e1, p1, accP[ri]);
                            accN[ri] = fmaf(e0, q0, accN[ri]);
                            accN[ri] = fmaf(e1, q1, accN[ri]);
                            accC[ri] += p0 + p1;
                        }
                    }
                }
            }
        }
        __syncthreads();
    }

    // ---------------- writeback: reduce over t-quad, one atomic set ----------------
    if (wid < 8) {
        #pragma unroll
        for (int ri = 0; ri < 8; ri++) {
            float pp = accP[ri], nn = accN[ri], pc = accC[ri];
            pp += __shfl_xor_sync(0xFFFFFFFFu, pp, 1);
            pp += __shfl_xor_sync(0xFFFFFFFFu, pp, 2);
            nn += __shfl_xor_sync(0xFFFFFFFFu, nn, 1);
            nn += __shfl_xor_sync(0xFFFFFFFFu, nn, 2);
            pc += __shfl_xor_sync(0xFFFFFFFFu, pc, 1);
            pc += __shfl_xor_sync(0xFFFFFFFFu, pc, 2);
            if (t == 0) {
                int row = i0 + wm * 64 + (ri >> 1) * 16 + (ri & 1) * 8 + g;
                atomicAdd(&g_pos[row], pp);
                atomicAdd(&g_neg[row], nn);
                atomicAdd(&g_pcnt[row], pc);
            }
        }
    }
}

// ============================================================
// Kernel 3: loss = -mean( log(pos/(pos+neg)) / pcnt )
// ============================================================
__global__ void __launch_bounds__(256) finalize_kernel(float* __restrict__ out) {
    int tid = threadIdx.x;
    double s = 0.0;
    for (int r = tid; r < N_ROWS; r += 256) {
        float P = g_pos[r], Nn = g_neg[r], C = g_pcnt[r];
        s += (double)(logf(P / (P + Nn)) / C);
    }
    __shared__ double red[256];
    red[tid] = s;
    __syncthreads();
    for (int o = 128; o; o >>= 1) {
        if (tid < o) red[tid] += red[tid + o];
        __syncthreads();
    }
    if (tid == 0) out[0] = (float)(-red[0] / (double)N_ROWS);
}

// ============================================================
extern "C" void kernel_launch(void* const* d_in, const int* in_sizes, int n_in,
                              void* d_out, int out_size) {
    const float* features = (const float*)d_in[0];
    const int* pmask = (const int*)d_in[1];
    const int* nmask = (const int*)d_in[2];
    float* out = (float*)d_out;

    cudaFuncSetAttribute(ssntxent_main,
                         cudaFuncAttributeMaxDynamicSharedMemorySize, SMEM_TOTAL);

    normalize_kernel<<<1024, 256>>>(features);
    ssntxent_main<<<dim3(2, 64), 512, SMEM_TOTAL>>>(pmask, nmask, 0);
    ssntxent_main<<<dim3(2, 64), 512, SMEM_TOTAL>>>(pmask, nmask, 16);
    finalize_kernel<<<1, 256>>>(out);
}

// round 15
// speedup vs baseline: 1.7672x; 1.2276x over previous
#include <cuda_runtime.h>
#include <cuda_bf16.h>
#include <cstdint>

#define N_ROWS 8192
#define DIM    128

// ---- dynamic smem layout ----
#define OFF_A      0                        // 128x128 bf16 A strip (32KB), swizzled
#define OFF_B      32768                    // 2 x 32KB B tiles
#define STRIDE_M   132                      // mask row stride (33 words)
#define SM_M_BYTES (128 * STRIDE_M)         // 16896
#define OFF_M      (32768 + 2 * 32768)      // 98304
#define SMEM_TOTAL (OFF_M + 2 * SM_M_BYTES) // 132096

// -------- scratch (device globals: allocation-free) --------
__device__ __nv_bfloat16 g_fnb[N_ROWS * DIM];   // normalized features (bf16)
__device__ __nv_bfloat16 g_fna[N_ROWS * DIM];   // normalized * 1/(T*ln2) (bf16)
__device__ float  g_pos[N_ROWS];
__device__ float  g_neg[N_ROWS];
__device__ float  g_pcnt[N_ROWS];
__device__ double g_loss;

// ---------------- helpers ----------------
__device__ __forceinline__ float ex2f_fast(float x) {
    float r; asm("ex2.approx.ftz.f32 %0, %1;" : "=f"(r) : "f"(x)); return r;
}
__device__ __forceinline__ void cp_async16(unsigned smem_addr, const void* gptr) {
    asm volatile("cp.async.cg.shared.global [%0], [%1], 16;\n" :: "r"(smem_addr), "l"(gptr));
}
__device__ __forceinline__ uint32_t smem_u32(const void* p) {
    uint32_t a;
    asm("{ .reg .u64 t; cvta.to.shared.u64 t, %1; cvt.u32.u64 %0, t; }" : "=r"(a) : "l"(p));
    return a;
}
__device__ __forceinline__ void ldsm_x4(unsigned* r, uint32_t addr) {
    asm volatile("ldmatrix.sync.aligned.m8n8.x4.shared.b16 {%0,%1,%2,%3}, [%4];"
                 : "=r"(r[0]), "=r"(r[1]), "=r"(r[2]), "=r"(r[3]) : "r"(addr));
}
__device__ __forceinline__ void mma_bf16(float* d, const unsigned* a, const unsigned* b) {
    asm volatile(
        "mma.sync.aligned.m16n8k16.row.col.f32.bf16.bf16.f32 "
        "{%0,%1,%2,%3}, {%4,%5,%6,%7}, {%8,%9}, {%0,%1,%2,%3};\n"
        : "+f"(d[0]), "+f"(d[1]), "+f"(d[2]), "+f"(d[3])
        : "r"(a[0]), "r"(a[1]), "r"(a[2]), "r"(a[3]), "r"(b[0]), "r"(b[1]));
}
// swizzled byte offset within a 128x128 bf16 tile: row r (0..127), 16B chunk c (0..15)
__device__ __forceinline__ unsigned tile_off(int r, int c) {
    return (unsigned)(r * 256 + ((c ^ (r & 7)) << 4));
}

// ============================================================
// Kernel 1: normalize rows -> bf16 (plain + K2-prescaled), zero accumulators
// ============================================================
__global__ void __launch_bounds__(256) normalize_kernel(const float* __restrict__ f) {
    if (blockIdx.x == 0 && threadIdx.x == 0) g_loss = 0.0;
    int g = blockIdx.x * 256 + threadIdx.x;
    if (g < N_ROWS) { g_pos[g] = 0.f; g_neg[g] = 0.f; g_pcnt[g] = 0.f; }
    int row = blockIdx.x * 8 + (threadIdx.x >> 5);
    int lane = threadIdx.x & 31;
    const float K2 = 20.6100944444973f;   // 1 / (0.07 * ln 2)
    float4 v = *(const float4*)(f + row * DIM + lane * 4);
    float ss = fmaf(v.x, v.x, fmaf(v.y, v.y, fmaf(v.z, v.z, v.w * v.w)));
    #pragma unroll
    for (int o = 16; o; o >>= 1) ss += __shfl_xor_sync(0xFFFFFFFFu, ss, o);
    float s = 1.0f / fmaxf(sqrtf(ss), 1e-8f);
    unsigned lo, hi;  // cvt packs: first source -> high half
    asm("cvt.rn.bf16x2.f32 %0, %1, %2;" : "=r"(lo) : "f"(v.y * s), "f"(v.x * s));
    asm("cvt.rn.bf16x2.f32 %0, %1, %2;" : "=r"(hi) : "f"(v.w * s), "f"(v.z * s));
    uint2 o2; o2.x = lo; o2.y = hi;
    *(uint2*)(g_fnb + row * DIM + lane * 4) = o2;
    float sk = s * K2;
    asm("cvt.rn.bf16x2.f32 %0, %1, %2;" : "=r"(lo) : "f"(v.y * sk), "f"(v.x * sk));
    asm("cvt.rn.bf16x2.f32 %0, %1, %2;" : "=r"(hi) : "f"(v.w * sk), "f"(v.z * sk));
    o2.x = lo; o2.y = hi;
    *(uint2*)(g_fna + row * DIM + lane * 4) = o2;
}

// ============================================================
// Kernel 2: fused bf16-MMA GEMM + exp + masked row-sums.
// grid dim3(2, 64); 512 threads: warps 0-7 consumers (2x4 grid, 64x32 tiles,
// two 32-row halves), warps 8-15 producers (16 mask rows each).
// ============================================================
__global__ void __launch_bounds__(512, 1)
ssntxent_main(const int* __restrict__ pmask, const int* __restrict__ nmask) {
    extern __shared__ char smem[];
    const int tid  = threadIdx.x;
    const int wid  = tid >> 5;
    const int lane = tid & 31;
    const int i0   = blockIdx.y * 128;
    const int cgb  = blockIdx.x * 4096;
    const uint32_t smem_base = smem_u32(smem);

    // ---------------- producers (warps 8-15) ----------------
    auto produceB = [&](int jt, int b) {
        const __nv_bfloat16* src = g_fnb + (cgb + jt * 128) * DIM;
        unsigned dbase = smem_base + OFF_B + (unsigned)b * 32768u;
        int tIdx = (wid - 8) * 32 + lane;                  // 0..255
        #pragma unroll
        for (int k = 0; k < 8; k++) {
            int idx = tIdx + k * 256;                      // 0..2047
            int r = idx >> 4, c = idx & 15;
            cp_async16(dbase + tile_off(r, c), src + r * DIM + c * 8);
        }
        asm volatile("cp.async.commit_group;\n");
    };
    auto produceM = [&](int jt, int b) {
        const int c0 = cgb + jt * 128;
        unsigned char* mdst = (unsigned char*)smem + OFF_M + b * SM_M_BYTES;
        const int pwid = wid - 8;                          // 0..7
        const int col = c0 + 4 * lane;
        #pragma unroll 1
        for (int b2 = 0; b2 < 2; b2++) {
            int4 a[8], bb[8];
            #pragma unroll
            for (int u = 0; u < 8; u++) {
                int rl = pwid * 16 + b2 * 8 + u;
                int off = (i0 + rl) * N_ROWS + col;
                a[u]  = *(const int4*)(pmask + off);
                bb[u] = *(const int4*)(nmask + off);
            }
            #pragma unroll
            for (int u = 0; u < 8; u++) {
                int rl = pwid * 16 + b2 * 8 + u;
                unsigned v = (unsigned)((a[u].x & 1)         | ((bb[u].x & 1) << 1)
                                      | ((a[u].y & 1) << 8)  | ((bb[u].y & 1) << 9)
                                      | ((a[u].z & 1) << 16) | ((bb[u].z & 1) << 17)
                                      | ((a[u].w & 1) << 24) | ((bb[u].w & 1) << 25));
                int d = (i0 + rl) - col;
                if ((unsigned)d < 4u) v &= ~(3u << (d * 8));
                *(unsigned*)(mdst + rl * STRIDE_M + 4 * lane) = v;
            }
        }
    };

    // ---------------- prologue ----------------
    if (wid < 8) {
        // consumers fill persistent A strip (K2-prescaled rows i0..i0+127)
        for (int idx = tid; idx < 2048; idx += 256) {
            int r = idx >> 4, c = idx & 15;
            uint4 v = *(const uint4*)(g_fna + (i0 + r) * DIM + c * 8);
            *(uint4*)(smem + OFF_A + tile_off(r, c)) = v;
        }
    } else {
        produceB(0, 0);
        asm volatile("cp.async.wait_group 0;\n" ::: "memory");
        produceM(0, 0);
    }
    __syncthreads();

    // consumer lane geometry
    const int wm = wid >> 2, wn = wid & 3;
    const int g = lane >> 2, t = lane & 3;
    const int arow = wm * 64 + ((lane >> 3) & 1) * 8 + (lane & 7);   // + (2*mh+mf)*16
    const uint32_t aBase = smem_base + OFF_A + (unsigned)(arow * 256);
    const int achunk = (lane >> 4);                                  // +2*kk, ^ sx
    const int brow0 = wn * 32 + ((lane >> 4) << 3) + (lane & 7);     // + p*16
    const int bchunk = (lane >> 3) & 1;                              // +2*kk, ^ sx
    const int sx = lane & 7;

    // persistent per-thread row accumulators
    float accP[8], accN[8];
    int   cnt[8];
    #pragma unroll
    for (int i = 0; i < 8; i++) { accP[i] = 0.f; accN[i] = 0.f; cnt[i] = 0; }

    // ---------------- main pipeline over 32 j-tiles ----------------
    for (int jj = 0; jj < 32; jj++) {
        const int buf = jj & 1;
        if (wid >= 8) {
            if (jj + 1 < 32) {
                produceB(jj + 1, buf ^ 1);
                produceM(jj + 1, buf ^ 1);
                asm volatile("cp.async.wait_group 0;\n" ::: "memory");
            }
        } else {
            const uint32_t bBase = smem_base + OFF_B + (unsigned)buf * 32768u
                                 + (unsigned)(brow0 * 256);
            const unsigned char* Ms =
                (const unsigned char*)smem + OFF_M + buf * SM_M_BYTES;

            #pragma unroll
            for (int mh = 0; mh < 2; mh++) {              // two 32-row halves
                float acc[2][4][4];
                #pragma unroll
                for (int mf = 0; mf < 2; mf++)
                    #pragma unroll
                    for (int nf = 0; nf < 4; nf++)
                        #pragma unroll
                        for (int e = 0; e < 4; e++) acc[mf][nf][e] = 0.f;

                #pragma unroll
                for (int kk = 0; kk < 8; kk++) {
                    unsigned a[2][4], b[2][4];
                    #pragma unroll
                    for (int mf = 0; mf < 2; mf++)
                        ldsm_x4(a[mf], aBase + (unsigned)((2 * mh + mf) * 16 * 256)
                                     + (unsigned)(((2 * kk + achunk) ^ sx) << 4));
                    #pragma unroll
                    for (int p = 0; p < 2; p++)
                        ldsm_x4(b[p], bBase + (unsigned)(p * 16 * 256)
                                    + (unsigned)(((2 * kk + bchunk) ^ sx) << 4));
                    #pragma unroll
                    for (int mf = 0; mf < 2; mf++) {
                        mma_bf16(acc[mf][0], a[mf], &b[0][0]);
                        mma_bf16(acc[mf][1], a[mf], &b[0][2]);
                        mma_bf16(acc[mf][2], a[mf], &b[1][0]);
                        mma_bf16(acc[mf][3], a[mf], &b[1][2]);
                    }
                }

                // epilogue: exp (arg already scaled) + masked sums
                #pragma unroll
                for (int mf = 0; mf < 2; mf++) {
                    #pragma unroll
                    for (int h = 0; h < 2; h++) {
                        const int ri = (2 * mh + mf) * 2 + h;
                        const int rl = wm * 64 + (2 * mh + mf) * 16 + 8 * h + g;
                        const unsigned char* Mrow = Ms + rl * STRIDE_M + wn * 32 + 2 * t;
                        #pragma unroll
                        for (int nf = 0; nf < 4; nf++) {
                            unsigned m = *(const unsigned short*)(Mrow + nf * 8);
                            float e0 = ex2f_fast(acc[mf][nf][2 * h + 0]);
                            float e1 = ex2f_fast(acc[mf][nf][2 * h + 1]);
                            // 0/1 -> 0.0f/1.0f via single AND + IMAD each
                            float p0 = __uint_as_float((m & 0x001u) * 0x3f800000u);
                            float q0 = __uint_as_float((m & 0x002u) * 0x1fc00000u);
                            float p1 = __uint_as_float((m & 0x100u) * 0x003f8000u);
                            float q1 = __uint_as_float((m & 0x200u) * 0x001fc000u);
                            accP[ri] = fmaf(e0, p0, accP[ri]);
                            accP[ri] = fmaf(e1, p1, accP[ri]);
                            accN[ri] = fmaf(e0, q0, accN[ri]);
                            accN[ri] = fmaf(e1, q1, accN[ri]);
                            cnt[ri] += __popc(m & 0x101u);
                        }
                    }
                }
            }
        }
        __syncthreads();
    }

    // ---------------- writeback: reduce over t-quad, one atomic set ----------------
    if (wid < 8) {
        #pragma unroll
        for (int ri = 0; ri < 8; ri++) {
            float pp = accP[ri], nn = accN[ri], pc = (float)cnt[ri];
            pp += __shfl_xor_sync(0xFFFFFFFFu, pp, 1);
            pp += __shfl_xor_sync(0xFFFFFFFFu, pp, 2);
            nn += __shfl_xor_sync(0xFFFFFFFFu, nn, 1);
            nn += __shfl_xor_sync(0xFFFFFFFFu, nn, 2);
            pc += __shfl_xor_sync(0xFFFFFFFFu, pc, 1);
            pc += __shfl_xor_sync(0xFFFFFFFFu, pc, 2);
            if (t == 0) {
                int row = i0 + wm * 64 + (ri >> 1) * 16 + (ri & 1) * 8 + g;
                atomicAdd(&g_pos[row], pp);
                atomicAdd(&g_neg[row], nn);
                atomicAdd(&g_pcnt[row], pc);
            }
        }
    }
}

// ============================================================
// Kernel 3a: parallel partial loss; 3b: writer
// ============================================================
__global__ void __launch_bounds__(256) finalize_partial() {
    int r = blockIdx.x * 256 + threadIdx.x;    // 32 blocks x 256 = 8192 rows
    float P = g_pos[r], Nn = g_neg[r], C = g_pcnt[r];
    double s = (double)(logf(P / (P + Nn)) / C);
    __shared__ double red[256];
    red[threadIdx.x] = s;
    __syncthreads();
    for (int o = 128; o; o >>= 1) {
        if (threadIdx.x < o) red[threadIdx.x] += red[threadIdx.x + o];
        __syncthreads();
    }
    if (threadIdx.x == 0) atomicAdd(&g_loss, red[0]);
}
__global__ void finalize_write(float* __restrict__ out) {
    out[0] = (float)(-g_loss / (double)N_ROWS);
}

// ============================================================
extern "C" void kernel_launch(void* const* d_in, const int* in_sizes, int n_in,
                              void* d_out, int out_size) {
    const float* features = (const float*)d_in[0];
    const int* pmask = (const int*)d_in[1];
    const int* nmask = (const int*)d_in[2];
    float* out = (float*)d_out;

    cudaFuncSetAttribute(ssntxent_main,
                         cudaFuncAttributeMaxDynamicSharedMemorySize, SMEM_TOTAL);

    normalize_kernel<<<1024, 256>>>(features);
    ssntxent_main<<<dim3(2, 64), 512, SMEM_TOTAL>>>(pmask, nmask);
    finalize_partial<<<32, 256>>>();
    finalize_write<<<1, 1>>>(out);
}